// round 2
// baseline (speedup 1.0000x reference)
#include <cuda_runtime.h>
#include <cuda_bf16.h>

// Problem constants (fixed by the reference)
#define T_DIM 512
#define B_DIM 32
#define I_DIM 512
#define H_DIM 512
#define M_DIM (T_DIM * B_DIM)   // 16384 rows of x (flattened (T,B))
#define N_DIM (3 * H_DIM)       // 1536 gate columns
#define K_DIM I_DIM             // 512

// Scratch: gx = x @ W_ih^T, (M, 3H) fp32 = 96 MB
__device__ float g_gx[(size_t)M_DIM * N_DIM];

// ---------------------------------------------------------------------------
// Phase 1: SGEMM  C[m][n] = sum_k A[m][k] * B[n][k]
// A: (M, K) row-major (x flattened), B: (N, K) row-major (W_ih), C: (M, N)
// Tiles: 128x64, BK=32, 256 threads, 8x4 microtile per thread.
// ---------------------------------------------------------------------------
#define BM 128
#define BN 64
#define BK 32

__global__ __launch_bounds__(256, 2)
void gemm_kernel(const float* __restrict__ A, const float* __restrict__ B)
{
    __shared__ float As[BK][BM + 4];   // +4 keeps rows 16B-aligned, limits conflicts
    __shared__ float Bs[BK][BN + 4];

    const int tid = threadIdx.x;
    const int bm  = blockIdx.x * BM;
    const int bn  = blockIdx.y * BN;

    const int tx = tid & 15;    // 0..15 -> 4 cols each
    const int ty = tid >> 4;    // 0..15 -> 8 rows each

    const int lcol = tid & 31;  // k within tile (coalesced 128B global reads)
    const int lrow = tid >> 5;  // base row, stride 8

    float acc[8][4];
#pragma unroll
    for (int i = 0; i < 8; ++i)
#pragma unroll
        for (int j = 0; j < 4; ++j) acc[i][j] = 0.f;

    for (int k0 = 0; k0 < K_DIM; k0 += BK) {
        // Load A tile (128 x 32) transposed into As[k][m]
#pragma unroll
        for (int i = 0; i < 16; ++i) {
            int r = lrow + i * 8;
            As[lcol][r] = A[(size_t)(bm + r) * K_DIM + k0 + lcol];
        }
        // Load B tile (64 x 32) transposed into Bs[k][n]
#pragma unroll
        for (int i = 0; i < 8; ++i) {
            int r = lrow + i * 8;
            Bs[lcol][r] = B[(size_t)(bn + r) * K_DIM + k0 + lcol];
        }
        __syncthreads();

#pragma unroll
        for (int k = 0; k < BK; ++k) {
            float4 a0 = *reinterpret_cast<const float4*>(&As[k][ty * 8]);
            float4 a1 = *reinterpret_cast<const float4*>(&As[k][ty * 8 + 4]);
            float4 b0 = *reinterpret_cast<const float4*>(&Bs[k][tx * 4]);
            float a[8] = {a0.x, a0.y, a0.z, a0.w, a1.x, a1.y, a1.z, a1.w};
            float bb[4] = {b0.x, b0.y, b0.z, b0.w};
#pragma unroll
            for (int i = 0; i < 8; ++i)
#pragma unroll
                for (int j = 0; j < 4; ++j)
                    acc[i][j] = fmaf(a[i], bb[j], acc[i][j]);
        }
        __syncthreads();
    }

    // Store 8x4 microtile as float4 rows
#pragma unroll
    for (int i = 0; i < 8; ++i) {
        float4 v = make_float4(acc[i][0], acc[i][1], acc[i][2], acc[i][3]);
        *reinterpret_cast<float4*>(
            &g_gx[(size_t)(bm + ty * 8 + i) * N_DIM + bn + tx * 4]) = v;
    }
}

// ---------------------------------------------------------------------------
// Phase 2: sequential scan over T. One thread per (b, h) element.
//   r = sigmoid(gr + w_r*h); z = sigmoid(gz + w_z*h)
//   n = tanh(gn + r*(w_n*h)); h = (1-z)*n + z*h
// out layout: (T, B, H) then h_last (B, H) appended.
// ---------------------------------------------------------------------------
__device__ __forceinline__ float sigmoid_f(float x)
{
    return 1.0f / (1.0f + __expf(-x));
}

__global__ __launch_bounds__(256)
void scan_kernel(const float* __restrict__ h0,
                 const float* __restrict__ w_hh,
                 float* __restrict__ out)
{
    const int idx = blockIdx.x * blockDim.x + threadIdx.x;  // 0..16383
    const int b = idx >> 9;          // / H_DIM
    const int h = idx & (H_DIM - 1); // % H_DIM

    const float wr = w_hh[h];
    const float wz = w_hh[H_DIM + h];
    const float wn = w_hh[2 * H_DIM + h];

    float hs = h0[idx];

    const float* g = g_gx + (size_t)b * N_DIM + h;   // row m = t*B + b
    float* o = out + idx;

#pragma unroll 4
    for (int t = 0; t < T_DIM; ++t) {
        float gr = g[0];
        float gz = g[H_DIM];
        float gn = g[2 * H_DIM];
        g += (size_t)B_DIM * N_DIM;

        float r = sigmoid_f(fmaf(wr, hs, gr));
        float z = sigmoid_f(fmaf(wz, hs, gz));
        float n = tanhf(fmaf(r, wn * hs, gn));
        hs = fmaf(z, hs - n, n);   // (1-z)*n + z*h = n + z*(h - n)

        *o = hs;
        o += B_DIM * H_DIM;
    }

    // h_last appended after the (T,B,H) block
    out[(size_t)T_DIM * B_DIM * H_DIM + idx] = hs;
}

// ---------------------------------------------------------------------------
// Launch
// Inputs (metadata order): x (T*B*I), h0 (B*H), W_ih (3H*I), w_hh (3*H)
// Output: out (T*B*H) ++ h_last (B*H), fp32
// ---------------------------------------------------------------------------
extern "C" void kernel_launch(void* const* d_in, const int* in_sizes, int n_in,
                              void* d_out, int out_size)
{
    const float* x    = (const float*)d_in[0];
    const float* h0   = (const float*)d_in[1];
    const float* W_ih = (const float*)d_in[2];
    const float* w_hh = (const float*)d_in[3];
    float* out = (float*)d_out;

    dim3 grid(M_DIM / BM, N_DIM / BN);   // 128 x 24
    gemm_kernel<<<grid, 256>>>(x, W_ih);

    scan_kernel<<<(B_DIM * H_DIM) / 256, 256>>>(h0, w_hh, out);
}

// round 3
// speedup vs baseline: 2.5132x; 2.5132x over previous
#include <cuda_runtime.h>
#include <cuda_bf16.h>
#include <cstdint>

// Problem constants
#define T_DIM 512
#define B_DIM 32
#define I_DIM 512
#define H_DIM 512
#define M_DIM (T_DIM * B_DIM)   // 16384
#define N_DIM (3 * H_DIM)       // 1536
#define K_DIM I_DIM             // 512

// Scratch buffers (static __device__ per allocation rules)
__device__ float g_gx[(size_t)M_DIM * N_DIM];                              // 96 MB
__device__ __align__(16) __nv_bfloat16 g_Ahi[(size_t)M_DIM * K_DIM];       // 16.8 MB
__device__ __align__(16) __nv_bfloat16 g_Alo[(size_t)M_DIM * K_DIM];
__device__ __align__(16) __nv_bfloat16 g_Bhi[(size_t)N_DIM * K_DIM];       // 1.6 MB
__device__ __align__(16) __nv_bfloat16 g_Blo[(size_t)N_DIM * K_DIM];

// ---------------------------------------------------------------------------
// Phase 0: split fp32 -> bf16 (hi, lo) pairs.  v = hi + lo + O(2^-17 |v|)
// ---------------------------------------------------------------------------
__device__ __forceinline__ void split_impl(const float* __restrict__ src,
                                           __nv_bfloat16* __restrict__ hi,
                                           __nv_bfloat16* __restrict__ lo,
                                           int n4)
{
    int i = blockIdx.x * blockDim.x + threadIdx.x;
    if (i >= n4) return;
    float4 v = reinterpret_cast<const float4*>(src)[i];
    float vs[4] = {v.x, v.y, v.z, v.w};
    __nv_bfloat16 h[4], l[4];
#pragma unroll
    for (int j = 0; j < 4; ++j) {
        h[j] = __float2bfloat16(vs[j]);
        l[j] = __float2bfloat16(vs[j] - __bfloat162float(h[j]));
    }
    reinterpret_cast<__nv_bfloat162*>(hi)[2 * i]     = __halves2bfloat162(h[0], h[1]);
    reinterpret_cast<__nv_bfloat162*>(hi)[2 * i + 1] = __halves2bfloat162(h[2], h[3]);
    reinterpret_cast<__nv_bfloat162*>(lo)[2 * i]     = __halves2bfloat162(l[0], l[1]);
    reinterpret_cast<__nv_bfloat162*>(lo)[2 * i + 1] = __halves2bfloat162(l[2], l[3]);
}

__global__ void split_x_kernel(const float* __restrict__ src)
{
    split_impl(src, g_Ahi, g_Alo, (M_DIM * K_DIM) / 4);
}
__global__ void split_w_kernel(const float* __restrict__ src)
{
    split_impl(src, g_Bhi, g_Blo, (N_DIM * K_DIM) / 4);
}

// ---------------------------------------------------------------------------
// Phase 1: tensor-core GEMM  gx[m][n] = sum_k x[m][k] * W[n][k]
// Split-bf16: C = Ah*Bh + Ah*Bl + Al*Bh  (fp32 accum), rel err ~1e-5.
// CTA tile 128x128, BK=32, 8 warps (4x2), warp tile 32x64.
// smem rows padded to 80B (40 bf16) -> conflict-free ldmatrix.
// ---------------------------------------------------------------------------
#define GBM 128
#define GBN 128
#define GBK 32
#define LDS_B 80                 // bytes per smem row (64B data + 16B pad)
#define ARR_B (128 * LDS_B)      // 10240 bytes per array
#define STAGE_B (4 * ARR_B)      // 40960 bytes per stage (Ahi,Alo,Bhi,Blo)
#define SMEM_TOTAL (2 * STAGE_B) // 81920

__device__ __forceinline__ void ldsm4(uint32_t* r, uint32_t addr)
{
    asm volatile("ldmatrix.sync.aligned.m8n8.x4.shared.b16 {%0,%1,%2,%3}, [%4];"
                 : "=r"(r[0]), "=r"(r[1]), "=r"(r[2]), "=r"(r[3]) : "r"(addr));
}

__device__ __forceinline__ void mma16816(float* c, const uint32_t* a, const uint32_t* b)
{
    asm volatile("mma.sync.aligned.m16n8k16.row.col.f32.bf16.bf16.f32 "
                 "{%0,%1,%2,%3},{%4,%5,%6,%7},{%8,%9},{%0,%1,%2,%3};"
                 : "+f"(c[0]), "+f"(c[1]), "+f"(c[2]), "+f"(c[3])
                 : "r"(a[0]), "r"(a[1]), "r"(a[2]), "r"(a[3]),
                   "r"(b[0]), "r"(b[1]));
}

extern __shared__ char g_smem[];

__global__ __launch_bounds__(256)
void gemm_kernel()
{
    const int tid  = threadIdx.x;
    const int lane = tid & 31;
    const int warp = tid >> 5;
    const int wm   = warp & 3;   // 0..3 (M dir)
    const int wn   = warp >> 2;  // 0..1 (N dir)
    const int bm   = blockIdx.x * GBM;
    const int bn   = blockIdx.y * GBN;

    const uint32_t sbase = (uint32_t)__cvta_generic_to_shared(g_smem);

    float acc[2][8][4];
#pragma unroll
    for (int i = 0; i < 2; ++i)
#pragma unroll
        for (int j = 0; j < 8; ++j)
#pragma unroll
            for (int q = 0; q < 4; ++q) acc[i][j][q] = 0.f;

    // --- async stage loader: 2048 x 16B chunks per stage, 8 per thread ---
    auto load_stage = [&](int it, int stage) {
        const int k0 = it * GBK;
        const uint32_t sdst = sbase + stage * STAGE_B;
#pragma unroll
        for (int i = 0; i < 8; ++i) {
            int cid = i * 256 + tid;
            int arr = cid >> 9;        // 0..3 (constant per unrolled i)
            int rem = cid & 511;
            int r   = rem >> 2;        // 0..127
            int c   = rem & 3;         // 16B chunk within 64B row
            const __nv_bfloat16* gsrc;
            if (arr == 0)      gsrc = g_Ahi + (size_t)(bm + r) * K_DIM + k0 + c * 8;
            else if (arr == 1) gsrc = g_Alo + (size_t)(bm + r) * K_DIM + k0 + c * 8;
            else if (arr == 2) gsrc = g_Bhi + (size_t)(bn + r) * K_DIM + k0 + c * 8;
            else               gsrc = g_Blo + (size_t)(bn + r) * K_DIM + k0 + c * 8;
            uint32_t d = sdst + arr * ARR_B + r * LDS_B + c * 16;
            asm volatile("cp.async.cg.shared.global [%0], [%1], 16;"
                         :: "r"(d), "l"(gsrc));
        }
        asm volatile("cp.async.commit_group;");
    };

    auto compute_stage = [&](int stage) {
        const uint32_t sA = sbase + stage * STAGE_B;
#pragma unroll
        for (int s = 0; s < 2; ++s) {           // two k16 steps per BK=32
            uint32_t a_hi[2][4], a_lo[2][4];
#pragma unroll
            for (int i = 0; i < 2; ++i) {
                int row  = wm * 32 + i * 16 + (lane & 15);
                int colb = (s * 16 + ((lane >> 4) << 3)) * 2;
                ldsm4(a_hi[i], sA + 0 * ARR_B + row * LDS_B + colb);
                ldsm4(a_lo[i], sA + 1 * ARR_B + row * LDS_B + colb);
            }
            uint32_t b_hi[4][4], b_lo[4][4];
#pragma unroll
            for (int jj = 0; jj < 4; ++jj) {
                int row  = wn * 64 + jj * 16 + ((lane >> 4) << 3) + (lane & 7);
                int colb = (s * 16 + (((lane >> 3) & 1) << 3)) * 2;
                ldsm4(b_hi[jj], sA + 2 * ARR_B + row * LDS_B + colb);
                ldsm4(b_lo[jj], sA + 3 * ARR_B + row * LDS_B + colb);
            }
#pragma unroll
            for (int i = 0; i < 2; ++i)
#pragma unroll
                for (int jj = 0; jj < 4; ++jj)
#pragma unroll
                    for (int h2 = 0; h2 < 2; ++h2) {
                        int j = jj * 2 + h2;
                        mma16816(acc[i][j], a_hi[i], &b_hi[jj][h2 * 2]);
                        mma16816(acc[i][j], a_lo[i], &b_hi[jj][h2 * 2]);
                        mma16816(acc[i][j], a_hi[i], &b_lo[jj][h2 * 2]);
                    }
        }
    };

    load_stage(0, 0);
    const int NIT = K_DIM / GBK;   // 16
    for (int it = 0; it < NIT; ++it) {
        if (it + 1 < NIT) {
            load_stage(it + 1, (it + 1) & 1);
            asm volatile("cp.async.wait_group 1;");
        } else {
            asm volatile("cp.async.wait_group 0;");
        }
        __syncthreads();
        compute_stage(it & 1);
        __syncthreads();
    }

    // Epilogue: fp32 stores to g_gx
#pragma unroll
    for (int i = 0; i < 2; ++i)
#pragma unroll
        for (int j = 0; j < 8; ++j) {
            int r0 = bm + wm * 32 + i * 16 + (lane >> 2);
            int c0 = bn + wn * 64 + j * 8 + ((lane & 3) << 1);
            float2 v01 = make_float2(acc[i][j][0], acc[i][j][1]);
            float2 v23 = make_float2(acc[i][j][2], acc[i][j][3]);
            *reinterpret_cast<float2*>(g_gx + (size_t)r0 * N_DIM + c0)       = v01;
            *reinterpret_cast<float2*>(g_gx + (size_t)(r0 + 8) * N_DIM + c0) = v23;
        }
}

// ---------------------------------------------------------------------------
// Phase 2: sequential scan, fast approx math + double-buffered prefetch.
// ---------------------------------------------------------------------------
__device__ __forceinline__ float fex2(float x)
{
    float r; asm("ex2.approx.f32 %0, %1;" : "=f"(r) : "f"(x)); return r;
}
__device__ __forceinline__ float frcp(float x)
{
    float r; asm("rcp.approx.f32 %0, %1;" : "=f"(r) : "f"(x)); return r;
}
__device__ __forceinline__ float fsig(float x)
{
    // sigmoid(x) = 1 / (1 + 2^(-x*log2(e)))
    return frcp(1.0f + fex2(-1.4426950408889634f * x));
}
__device__ __forceinline__ float ftanh(float x)
{
    // tanh(x) = 2*sigmoid(2x) - 1   (error ~1e-6, vs tanh.approx ~6e-4)
    return fmaf(2.0f, fsig(2.0f * x), -1.0f);
}

__global__ __launch_bounds__(128)
void scan_kernel(const float* __restrict__ h0,
                 const float* __restrict__ w_hh,
                 float* __restrict__ out)
{
    const int idx = blockIdx.x * blockDim.x + threadIdx.x;  // 0..16383
    const int b = idx >> 9;
    const int h = idx & (H_DIM - 1);

    const float wr = w_hh[h];
    const float wz = w_hh[H_DIM + h];
    const float wn = w_hh[2 * H_DIM + h];

    float hs = h0[idx];

    const float* gbase = g_gx + (size_t)b * N_DIM + h;  // row m = t*B + b
    float* obase = out + idx;

    float bufA[24], bufB[24];

#define LOADB(buf, t0)                                                        \
    {                                                                         \
        _Pragma("unroll")                                                     \
        for (int j = 0; j < 8; ++j) {                                         \
            const float* p = gbase + (size_t)((t0) + j) * (B_DIM * N_DIM);    \
            buf[3 * j + 0] = __ldg(p);                                        \
            buf[3 * j + 1] = __ldg(p + H_DIM);                                \
            buf[3 * j + 2] = __ldg(p + 2 * H_DIM);                            \
        }                                                                     \
    }

#define STEPB(buf, t0)                                                        \
    {                                                                         \
        _Pragma("unroll")                                                     \
        for (int j = 0; j < 8; ++j) {                                         \
            float gr = buf[3 * j + 0];                                        \
            float gz = buf[3 * j + 1];                                        \
            float gn = buf[3 * j + 2];                                        \
            float r = fsig(fmaf(wr, hs, gr));                                 \
            float z = fsig(fmaf(wz, hs, gz));                                 \
            float n = ftanh(fmaf(r, wn * hs, gn));                            \
            hs = fmaf(z, hs - n, n);                                          \
            obase[(size_t)((t0) + j) * (B_DIM * H_DIM)] = hs;                 \
        }                                                                     \
    }

    LOADB(bufA, 0);
#pragma unroll 1
    for (int t0 = 0; t0 < T_DIM; t0 += 16) {
        LOADB(bufB, t0 + 8);
        STEPB(bufA, t0);
        if (t0 + 16 < T_DIM) LOADB(bufA, t0 + 16);
        STEPB(bufB, t0 + 8);
    }

    out[(size_t)T_DIM * B_DIM * H_DIM + idx] = hs;

#undef LOADB
#undef STEPB
}

// ---------------------------------------------------------------------------
// Launch.  Inputs: x (T*B*I), h0 (B*H), W_ih (3H*I), w_hh (3*H). Output fp32.
// ---------------------------------------------------------------------------
extern "C" void kernel_launch(void* const* d_in, const int* in_sizes, int n_in,
                              void* d_out, int out_size)
{
    const float* x    = (const float*)d_in[0];
    const float* h0   = (const float*)d_in[1];
    const float* W_ih = (const float*)d_in[2];
    const float* w_hh = (const float*)d_in[3];
    float* out = (float*)d_out;

    cudaFuncSetAttribute(gemm_kernel,
                         cudaFuncAttributeMaxDynamicSharedMemorySize, SMEM_TOTAL);

    int n4x = (M_DIM * K_DIM) / 4;
    int n4w = (N_DIM * K_DIM) / 4;
    split_x_kernel<<<(n4x + 255) / 256, 256>>>(x);
    split_w_kernel<<<(n4w + 255) / 256, 256>>>(W_ih);

    dim3 grid(M_DIM / GBM, N_DIM / GBN);   // 128 x 12
    gemm_kernel<<<grid, 256, SMEM_TOTAL>>>();

    scan_kernel<<<(B_DIM * H_DIM) / 128, 128>>>(h0, w_hh, out);
}

// round 5
// speedup vs baseline: 2.9988x; 1.1932x over previous
#include <cuda_runtime.h>
#include <cuda_bf16.h>
#include <cstdint>

// Problem constants
#define T_DIM 512
#define B_DIM 32
#define I_DIM 512
#define H_DIM 512
#define M_DIM (T_DIM * B_DIM)   // 16384
#define N_DIM (3 * H_DIM)       // 1536
#define K_DIM I_DIM             // 512

// gx is stored PRE-SCALED: gates r,z scaled by -log2(e), gate n by -2*log2(e)
#define C1F (-1.4426950408889634f)
#define C2F (-2.8853900817779268f)

// Scratch buffers (static __device__ per allocation rules)
__device__ float g_gx[(size_t)M_DIM * N_DIM];                              // 96 MB
__device__ __align__(16) __nv_bfloat16 g_Ahi[(size_t)M_DIM * K_DIM];
__device__ __align__(16) __nv_bfloat16 g_Alo[(size_t)M_DIM * K_DIM];
__device__ __align__(16) __nv_bfloat16 g_Bhi[(size_t)N_DIM * K_DIM];
__device__ __align__(16) __nv_bfloat16 g_Blo[(size_t)N_DIM * K_DIM];

// ---------------------------------------------------------------------------
// Phase 0: split fp32 -> bf16 (hi, lo) pairs.  v = hi + lo + O(2^-17 |v|)
// ---------------------------------------------------------------------------
__device__ __forceinline__ void split_impl(const float* __restrict__ src,
                                           __nv_bfloat16* __restrict__ hi,
                                           __nv_bfloat16* __restrict__ lo,
                                           int n4)
{
    int i = blockIdx.x * blockDim.x + threadIdx.x;
    if (i >= n4) return;
    float4 v = reinterpret_cast<const float4*>(src)[i];
    float vs[4] = {v.x, v.y, v.z, v.w};
    __nv_bfloat16 h[4], l[4];
#pragma unroll
    for (int j = 0; j < 4; ++j) {
        h[j] = __float2bfloat16(vs[j]);
        l[j] = __float2bfloat16(vs[j] - __bfloat162float(h[j]));
    }
    reinterpret_cast<__nv_bfloat162*>(hi)[2 * i]     = __halves2bfloat162(h[0], h[1]);
    reinterpret_cast<__nv_bfloat162*>(hi)[2 * i + 1] = __halves2bfloat162(h[2], h[3]);
    reinterpret_cast<__nv_bfloat162*>(lo)[2 * i]     = __halves2bfloat162(l[0], l[1]);
    reinterpret_cast<__nv_bfloat162*>(lo)[2 * i + 1] = __halves2bfloat162(l[2], l[3]);
}

__global__ void split_x_kernel(const float* __restrict__ src)
{
    split_impl(src, g_Ahi, g_Alo, (M_DIM * K_DIM) / 4);
}
__global__ void split_w_kernel(const float* __restrict__ src)
{
    split_impl(src, g_Bhi, g_Blo, (N_DIM * K_DIM) / 4);
}

// ---------------------------------------------------------------------------
// Phase 1: tensor-core GEMM (mma.sync HMMA path; tcgen05 not available at the
// harness's compute_103 PTX target).
// gx[m][n] = scale(n) * sum_k x[m][k] * W[n][k]
// Split-bf16: C = Ah*Bh + Ah*Bl + Al*Bh (fp32 accum), rel err ~1e-5.
// CTA tile 128x128, BK=32, 8 warps (4x2), warp tile 32x64.
// Grid is N-fastest so a wave's working set (~6MB) lives in L2.
// ---------------------------------------------------------------------------
#define GBM 128
#define GBN 128
#define GBK 32
#define LDS_B 80                 // bytes per smem row (64B data + 16B pad)
#define ARR_B (128 * LDS_B)      // 10240 bytes per array
#define STAGE_B (4 * ARR_B)      // 40960 bytes per stage (Ahi,Alo,Bhi,Blo)
#define SMEM_TOTAL (2 * STAGE_B) // 81920

__device__ __forceinline__ void ldsm4(uint32_t* r, uint32_t addr)
{
    asm volatile("ldmatrix.sync.aligned.m8n8.x4.shared.b16 {%0,%1,%2,%3}, [%4];"
                 : "=r"(r[0]), "=r"(r[1]), "=r"(r[2]), "=r"(r[3]) : "r"(addr));
}

__device__ __forceinline__ void mma16816(float* c, const uint32_t* a, const uint32_t* b)
{
    asm volatile("mma.sync.aligned.m16n8k16.row.col.f32.bf16.bf16.f32 "
                 "{%0,%1,%2,%3},{%4,%5,%6,%7},{%8,%9},{%0,%1,%2,%3};"
                 : "+f"(c[0]), "+f"(c[1]), "+f"(c[2]), "+f"(c[3])
                 : "r"(a[0]), "r"(a[1]), "r"(a[2]), "r"(a[3]),
                   "r"(b[0]), "r"(b[1]));
}

extern __shared__ char g_smem[];

__global__ __launch_bounds__(256)
void gemm_kernel()
{
    const int tid  = threadIdx.x;
    const int lane = tid & 31;
    const int warp = tid >> 5;
    const int wm   = warp & 3;   // 0..3 (M dir)
    const int wn   = warp >> 2;  // 0..1 (N dir)
    const int bn   = blockIdx.x * GBN;   // N fastest -> wave shares A/B via L2
    const int bm   = blockIdx.y * GBM;

    const uint32_t sbase = (uint32_t)__cvta_generic_to_shared(g_smem);

    float acc[2][8][4];
#pragma unroll
    for (int i = 0; i < 2; ++i)
#pragma unroll
        for (int j = 0; j < 8; ++j)
#pragma unroll
            for (int q = 0; q < 4; ++q) acc[i][j][q] = 0.f;

    // --- async stage loader: 2048 x 16B chunks per stage, 8 per thread ---
    auto load_stage = [&](int it, int stage) {
        const int k0 = it * GBK;
        const uint32_t sdst = sbase + stage * STAGE_B;
#pragma unroll
        for (int i = 0; i < 8; ++i) {
            int cid = i * 256 + tid;
            int arr = cid >> 9;        // 0..3 (constant per unrolled i)
            int rem = cid & 511;
            int r   = rem >> 2;        // 0..127
            int c   = rem & 3;         // 16B chunk within 64B row
            const __nv_bfloat16* gsrc;
            if (arr == 0)      gsrc = g_Ahi + (size_t)(bm + r) * K_DIM + k0 + c * 8;
            else if (arr == 1) gsrc = g_Alo + (size_t)(bm + r) * K_DIM + k0 + c * 8;
            else if (arr == 2) gsrc = g_Bhi + (size_t)(bn + r) * K_DIM + k0 + c * 8;
            else               gsrc = g_Blo + (size_t)(bn + r) * K_DIM + k0 + c * 8;
            uint32_t d = sdst + arr * ARR_B + r * LDS_B + c * 16;
            asm volatile("cp.async.cg.shared.global [%0], [%1], 16;"
                         :: "r"(d), "l"(gsrc));
        }
        asm volatile("cp.async.commit_group;");
    };

    auto compute_stage = [&](int stage) {
        const uint32_t sA = sbase + stage * STAGE_B;
#pragma unroll
        for (int s = 0; s < 2; ++s) {           // two k16 steps per BK=32
            uint32_t a_hi[2][4], a_lo[2][4];
#pragma unroll
            for (int i = 0; i < 2; ++i) {
                int row  = wm * 32 + i * 16 + (lane & 15);
                int colb = (s * 16 + ((lane >> 4) << 3)) * 2;
                ldsm4(a_hi[i], sA + 0 * ARR_B + row * LDS_B + colb);
                ldsm4(a_lo[i], sA + 1 * ARR_B + row * LDS_B + colb);
            }
            uint32_t b_hi[4][4], b_lo[4][4];
#pragma unroll
            for (int jj = 0; jj < 4; ++jj) {
                int row  = wn * 64 + jj * 16 + ((lane >> 4) << 3) + (lane & 7);
                int colb = (s * 16 + (((lane >> 3) & 1) << 3)) * 2;
                ldsm4(b_hi[jj], sA + 2 * ARR_B + row * LDS_B + colb);
                ldsm4(b_lo[jj], sA + 3 * ARR_B + row * LDS_B + colb);
            }
#pragma unroll
            for (int i = 0; i < 2; ++i)
#pragma unroll
                for (int jj = 0; jj < 4; ++jj)
#pragma unroll
                    for (int h2 = 0; h2 < 2; ++h2) {
                        int j = jj * 2 + h2;
                        mma16816(acc[i][j], a_hi[i], &b_hi[jj][h2 * 2]);
                        mma16816(acc[i][j], a_lo[i], &b_hi[jj][h2 * 2]);
                        mma16816(acc[i][j], a_hi[i], &b_lo[jj][h2 * 2]);
                    }
        }
    };

    load_stage(0, 0);
    const int NIT = K_DIM / GBK;   // 16
    for (int it = 0; it < NIT; ++it) {
        if (it + 1 < NIT) {
            load_stage(it + 1, (it + 1) & 1);
            asm volatile("cp.async.wait_group 1;");
        } else {
            asm volatile("cp.async.wait_group 0;");
        }
        __syncthreads();
        compute_stage(it & 1);
        __syncthreads();
    }

    // Epilogue: scale by gate constant, store fp32.
    // Gate boundary (n=1024) is a multiple of GBN, so scale is uniform per CTA.
    const float sc = (bn >= 2 * H_DIM) ? C2F : C1F;
#pragma unroll
    for (int i = 0; i < 2; ++i)
#pragma unroll
        for (int j = 0; j < 8; ++j) {
            int r0 = bm + wm * 32 + i * 16 + (lane >> 2);
            int c0 = bn + wn * 64 + j * 8 + ((lane & 3) << 1);
            float2 v01 = make_float2(sc * acc[i][j][0], sc * acc[i][j][1]);
            float2 v23 = make_float2(sc * acc[i][j][2], sc * acc[i][j][3]);
            *reinterpret_cast<float2*>(g_gx + (size_t)r0 * N_DIM + c0)       = v01;
            *reinterpret_cast<float2*>(g_gx + (size_t)(r0 + 8) * N_DIM + c0) = v23;
        }
}

// ---------------------------------------------------------------------------
// Phase 2: scan. Per-thread cp.async pipeline (depth 8) through smem.
// gx is pre-scaled, so each gate is rcp(1 + ex2(fma)) only.
//   r = sigmoid(gr + wr*h)   via  1/(1+2^(C1*(gr+wr*h)))  [C1 folded into gx,wr]
//   n = tanh(gn + r*wn*h) = 2*sigmoid(2*(...)) - 1         [2 folded via C2]
// ---------------------------------------------------------------------------
__device__ __forceinline__ float fex2(float x)
{
    float r; asm("ex2.approx.f32 %0, %1;" : "=f"(r) : "f"(x)); return r;
}
__device__ __forceinline__ float frcp(float x)
{
    float r; asm("rcp.approx.f32 %0, %1;" : "=f"(r) : "f"(x)); return r;
}

#define SCAN_DEPTH 8

__global__ __launch_bounds__(128)
void scan_kernel(const float* __restrict__ h0,
                 const float* __restrict__ w_hh,
                 float* __restrict__ out)
{
    __shared__ float sbuf[SCAN_DEPTH][3][128];   // 12 KB

    const int tid = threadIdx.x;
    const int idx = blockIdx.x * 128 + tid;      // 0..16383
    const int b = idx >> 9;
    const int h = idx & (H_DIM - 1);

    const float wrl = C1F * w_hh[h];
    const float wzl = C1F * w_hh[H_DIM + h];
    const float wnl = C2F * w_hh[2 * H_DIM + h];

    float hs = h0[idx];

    const float* gbase = g_gx + (size_t)b * N_DIM + h;  // + t*B*N per step
    const uint32_t sb = (uint32_t)__cvta_generic_to_shared(&sbuf[0][0][0]) + tid * 4;

    // prefetch timestep t into slot t % DEPTH (cp.async groups are per-thread)
    auto issue = [&](int t) {
        if (t < T_DIM) {
            const float* p = gbase + (size_t)t * (B_DIM * N_DIM);
            uint32_t d = sb + (t & (SCAN_DEPTH - 1)) * (3 * 128 * 4);
            asm volatile("cp.async.ca.shared.global [%0], [%1], 4;" :: "r"(d),        "l"(p));
            asm volatile("cp.async.ca.shared.global [%0], [%1], 4;" :: "r"(d + 512),  "l"(p + H_DIM));
            asm volatile("cp.async.ca.shared.global [%0], [%1], 4;" :: "r"(d + 1024), "l"(p + 2 * H_DIM));
        }
        asm volatile("cp.async.commit_group;");
    };

#pragma unroll
    for (int t = 0; t < SCAN_DEPTH; ++t) issue(t);

    float* o = out + idx;
#pragma unroll 1
    for (int t = 0; t < T_DIM; ++t) {
        asm volatile("cp.async.wait_group %0;" :: "n"(SCAN_DEPTH - 1));
        const int s = t & (SCAN_DEPTH - 1);
        float grp = sbuf[s][0][tid];
        float gzp = sbuf[s][1][tid];
        float gnp = sbuf[s][2][tid];

        float wnl_h = wnl * hs;                       // off critical path
        float r = frcp(1.0f + fex2(fmaf(wrl, hs, grp)));
        float z = frcp(1.0f + fex2(fmaf(wzl, hs, gzp)));
        float s2 = frcp(1.0f + fex2(fmaf(r, wnl_h, gnp)));
        float n = fmaf(2.0f, s2, -1.0f);
        hs = fmaf(z, hs - n, n);

        *o = hs;
        o += B_DIM * H_DIM;
        issue(t + SCAN_DEPTH);
    }

    out[(size_t)T_DIM * B_DIM * H_DIM + idx] = hs;
}

// ---------------------------------------------------------------------------
// Launch.  Inputs: x (T*B*I), h0 (B*H), W_ih (3H*I), w_hh (3*H). Output fp32.
// ---------------------------------------------------------------------------
extern "C" void kernel_launch(void* const* d_in, const int* in_sizes, int n_in,
                              void* d_out, int out_size)
{
    const float* x    = (const float*)d_in[0];
    const float* h0   = (const float*)d_in[1];
    const float* W_ih = (const float*)d_in[2];
    const float* w_hh = (const float*)d_in[3];
    float* out = (float*)d_out;

    cudaFuncSetAttribute(gemm_kernel,
                         cudaFuncAttributeMaxDynamicSharedMemorySize, SMEM_TOTAL);

    int n4x = (M_DIM * K_DIM) / 4;
    int n4w = (N_DIM * K_DIM) / 4;
    split_x_kernel<<<(n4x + 255) / 256, 256>>>(x);
    split_w_kernel<<<(n4w + 255) / 256, 256>>>(W_ih);

    dim3 grid(N_DIM / GBN, M_DIM / GBM);   // (12, 128), N fastest
    gemm_kernel<<<grid, 256, SMEM_TOTAL>>>();

    scan_kernel<<<(B_DIM * H_DIM) / 128, 128>>>(h0, w_hh, out);
}